// round 8
// baseline (speedup 1.0000x reference)
#include <cuda_runtime.h>
#include <cuda_bf16.h>
#include <cstdint>
#include <math.h>

#define BB 4
#define NSEQ 2048
#define CDIM 768
#define HH 12
#define DD 64
#define HIDD 3072
#define MROWS (BB * NSEQ)   // 8192

// ---------------- scratch ----------------
__device__ float g_h[MROWS * CDIM];
__device__ float g_q[MROWS * CDIM];
__device__ float g_k[MROWS * CDIM];
__device__ __nv_bfloat16 g_vb[MROWS * CDIM];   // V, bf16, [B,H,D,N] d-major
__device__ float g_o[MROWS * CDIM];
__device__ float g_x1[MROWS * CDIM];
__device__ float g_hid[MROWS * HIDD];
// tf32-rounded weights
__device__ float g_wqkv[3 * CDIM * CDIM];
__device__ float g_wproj[CDIM * CDIM];
__device__ float g_wfc1[HIDD * CDIM];
__device__ float g_wfc2[CDIM * HIDD];

__device__ __forceinline__ float to_tf32(float x) {
    float y;
    asm("cvt.rna.tf32.f32 %0, %1;" : "=f"(y) : "f"(x));
    return y;
}
__device__ __forceinline__ uint32_t smem_u32(const void* p) {
    uint32_t a;
    asm("{ .reg .u64 t; cvta.to.shared.u64 t, %1; cvt.u32.u64 %0, t; }" : "=r"(a) : "l"(p));
    return a;
}
__device__ __forceinline__ void mma_tf32(float* d, const uint32_t* a, const uint32_t* b) {
    asm volatile(
        "mma.sync.aligned.m16n8k8.row.col.f32.tf32.tf32.f32 "
        "{%0,%1,%2,%3}, {%4,%5,%6,%7}, {%8,%9}, {%0,%1,%2,%3};"
        : "+f"(d[0]), "+f"(d[1]), "+f"(d[2]), "+f"(d[3])
        : "r"(a[0]), "r"(a[1]), "r"(a[2]), "r"(a[3]), "r"(b[0]), "r"(b[1]));
}
__device__ __forceinline__ void mma_bf16(float* d, const uint32_t* a, uint32_t b0, uint32_t b1) {
    asm volatile(
        "mma.sync.aligned.m16n8k16.row.col.f32.bf16.bf16.f32 "
        "{%0,%1,%2,%3}, {%4,%5,%6,%7}, {%8,%9}, {%0,%1,%2,%3};"
        : "+f"(d[0]), "+f"(d[1]), "+f"(d[2]), "+f"(d[3])
        : "r"(a[0]), "r"(a[1]), "r"(a[2]), "r"(a[3]), "r"(b0), "r"(b1));
}
__device__ __forceinline__ void ldsm4(uint32_t* r, uint32_t addr) {
    asm volatile("ldmatrix.sync.aligned.m8n8.x4.shared.b16 {%0,%1,%2,%3}, [%4];"
                 : "=r"(r[0]), "=r"(r[1]), "=r"(r[2]), "=r"(r[3]) : "r"(addr));
}
__device__ __forceinline__ void cp16(uint32_t dst, const float* src) {
    asm volatile("cp.async.cg.shared.global [%0], [%1], 16;"
                 :: "r"(dst), "l"(__cvta_generic_to_global(src)));
}
#define CP_COMMIT() asm volatile("cp.async.commit_group;" ::: "memory")
#define CP_WAIT1()  asm volatile("cp.async.wait_group 1;" ::: "memory")

__device__ __forceinline__ uint32_t pack_bf16(float a, float b) {
    __nv_bfloat162 h = __floats2bfloat162_rn(a, b);
    return *(uint32_t*)&h;
}

// ---------------- weight tf32 pre-round ----------------
__global__ __launch_bounds__(256) void wcvt_kernel(
    const float* s0, float* d0, int n0, const float* s1, float* d1, int n1,
    const float* s2, float* d2, int n2, const float* s3, float* d3, int n3) {
    const float* s; float* d; int n;
    switch (blockIdx.y) {
        case 0: s = s0; d = d0; n = n0; break;
        case 1: s = s1; d = d1; n = n1; break;
        case 2: s = s2; d = d2; n = n2; break;
        default: s = s3; d = d3; n = n3; break;
    }
    int i = (blockIdx.x * 256 + threadIdx.x) * 4;
    if (i < n) {
        float4 v = *(const float4*)(s + i);
        v.x = to_tf32(v.x); v.y = to_tf32(v.y); v.z = to_tf32(v.z); v.w = to_tf32(v.w);
        *(float4*)(d + i) = v;
    }
}

// ---------------- cp.async tensor-core GEMM: C = A[M,K] * W[Nn,K]^T ----------------
#define GS 3
#define STG_B 32768
#define GEMM_SMEM (GS * STG_B)

template <int EPI>
__global__ __launch_bounds__(256, 2) void gemm_cp(
    const float* __restrict__ A, const float* __restrict__ W,
    const float* __restrict__ bias, const float* __restrict__ res,
    float* __restrict__ C, int M, int Nn, int K,
    float* __restrict__ qout, float* __restrict__ kout, __nv_bfloat16* __restrict__ vout) {
    extern __shared__ char sm[];
    uint32_t sb = smem_u32(sm);
    int tid = threadIdx.x, lane = tid & 31, wid = tid >> 5;
    int warpM = wid & 1, warpN = wid >> 1;
    int g = lane >> 2, t = lane & 3;
    int rowBase = blockIdx.y * 128, colBase = blockIdx.x * 128;

    float acc[4][4][4];
#pragma unroll
    for (int i = 0; i < 4; i++)
#pragma unroll
        for (int j = 0; j < 4; j++)
#pragma unroll
            for (int e = 0; e < 4; e++) acc[i][j][e] = 0.f;

    const int r0 = tid >> 3;
    const int c16 = tid & 7;
    const uint32_t csw = (uint32_t)((c16 ^ (r0 & 7)) << 4);
    const float* Ab = A + (size_t)rowBase * K + c16 * 4;
    const float* Wb = W + (size_t)colBase * K + c16 * 4;

    const int r7 = lane & 7;
    const int hiA = lane >> 4;
    const int hiB = (lane >> 3) & 1;
    uint32_t rbA[4], rbB[2];
#pragma unroll
    for (int mt = 0; mt < 4; mt++)
        rbA[mt] = (uint32_t)((warpM * 64 + mt * 16 + (lane & 15)) * 128);
#pragma unroll
    for (int p = 0; p < 2; p++)
        rbB[p] = (uint32_t)((warpN * 32 + p * 16 + (lane & 7) + ((lane >> 4) << 3)) * 128) + 16384;

    const int nc = K >> 5;
#pragma unroll
    for (int s = 0; s < GS - 1; s++) {
        uint32_t sA = sb + s * STG_B;
        const float* Ac = Ab + s * 32;
        const float* Wc = Wb + s * 32;
#pragma unroll
        for (int i = 0; i < 4; i++) {
            int r = r0 + i * 32;
            cp16(sA + r * 128 + csw, Ac + (size_t)r * K);
            cp16(sA + 16384 + r * 128 + csw, Wc + (size_t)r * K);
        }
        CP_COMMIT();
    }

    for (int c = 0; c < nc; c++) {
        CP_WAIT1();
        __syncthreads();
        int nxt = c + GS - 1;
        if (nxt < nc) {
            uint32_t sA = sb + (nxt % GS) * STG_B;
            const float* Ac = Ab + nxt * 32;
            const float* Wc = Wb + nxt * 32;
#pragma unroll
            for (int i = 0; i < 4; i++) {
                int r = r0 + i * 32;
                cp16(sA + r * 128 + csw, Ac + (size_t)r * K);
                cp16(sA + 16384 + r * 128 + csw, Wc + (size_t)r * K);
            }
        }
        CP_COMMIT();
        uint32_t stg = sb + (c % GS) * STG_B;
#pragma unroll
        for (int ks = 0; ks < 4; ks++) {
            uint32_t colA = (uint32_t)((((2 * ks + hiA) ^ r7)) << 4);
            uint32_t colB = (uint32_t)((((2 * ks + hiB) ^ r7)) << 4);
            uint32_t af[4][4], bf[2][4];
#pragma unroll
            for (int mt = 0; mt < 4; mt++) ldsm4(af[mt], stg + rbA[mt] + colA);
#pragma unroll
            for (int p = 0; p < 2; p++) ldsm4(bf[p], stg + rbB[p] + colB);
#pragma unroll
            for (int mt = 0; mt < 4; mt++)
#pragma unroll
                for (int nt = 0; nt < 4; nt++)
                    mma_tf32(acc[mt][nt], af[mt], &bf[nt >> 1][(nt & 1) * 2]);
        }
    }

#pragma unroll
    for (int mt = 0; mt < 4; mt++) {
        int rlo = rowBase + warpM * 64 + mt * 16 + g;
#pragma unroll
        for (int nt = 0; nt < 4; nt++) {
            int colb = colBase + warpN * 32 + nt * 8 + t * 2;
#pragma unroll
            for (int half = 0; half < 2; half++) {
                int row = rlo + half * 8;
                float v0 = acc[mt][nt][half * 2 + 0];
                float v1 = acc[mt][nt][half * 2 + 1];
                if (EPI == 0) {
                    int which = colb / CDIM;
                    int rem = colb - which * CDIM;
                    int h = rem >> 6, d0 = rem & 63;
                    int bq = row >> 11, n = row & 2047;
                    if (which == 2) {
                        // V bf16 d-major: [B,H,D,N]
                        __nv_bfloat16* dst = vout + (((size_t)bq * HH + h) * DD + d0) * NSEQ + n;
                        dst[0] = __float2bfloat16_rn(v0);
                        dst[NSEQ] = __float2bfloat16_rn(v1);
                    } else {
                        float scale = (which == 0) ? 0.125f : 1.0f;
                        float* dst = (which == 0 ? qout : kout) +
                                     ((((size_t)bq * HH + h) * NSEQ + n) * DD + d0);
                        *(float2*)dst = make_float2(to_tf32(v0 * scale), to_tf32(v1 * scale));
                    }
                } else if (EPI == 1) {
                    float2 bv = *(const float2*)(bias + colb);
                    float2 rv = *(const float2*)(res + (size_t)row * Nn + colb);
                    *(float2*)(C + (size_t)row * Nn + colb) =
                        make_float2(v0 + bv.x + rv.x, v1 + bv.y + rv.y);
                } else {
                    float2 bv = *(const float2*)(bias + colb);
                    float u0 = v0 + bv.x, u1 = v1 + bv.y;
                    float2 o;
                    o.x = to_tf32(0.5f * u0 * (1.0f + erff(u0 * 0.70710678f)));
                    o.y = to_tf32(0.5f * u1 * (1.0f + erff(u1 * 0.70710678f)));
                    *(float2*)(C + (size_t)row * Nn + colb) = o;
                }
            }
        }
    }
}

// ---------------- LayerNorm (tf32-rounded output) ----------------
__global__ __launch_bounds__(256) void ln_kernel(const float* __restrict__ X,
                                                 const float* __restrict__ gam,
                                                 const float* __restrict__ bet,
                                                 float* __restrict__ out) {
    int row = blockIdx.x;
    const float* xr = X + (size_t)row * CDIM;
    float v[3];
    float s = 0.f, s2 = 0.f;
#pragma unroll
    for (int i = 0; i < 3; i++) {
        v[i] = xr[threadIdx.x + i * 256];
        s += v[i];
        s2 += v[i] * v[i];
    }
#pragma unroll
    for (int o = 16; o > 0; o >>= 1) {
        s  += __shfl_xor_sync(0xffffffffu, s, o);
        s2 += __shfl_xor_sync(0xffffffffu, s2, o);
    }
    __shared__ float ws[8], ws2[8];
    int wid = threadIdx.x >> 5, lane = threadIdx.x & 31;
    if (lane == 0) { ws[wid] = s; ws2[wid] = s2; }
    __syncthreads();
    if (wid == 0) {
        s  = (lane < 8) ? ws[lane] : 0.f;
        s2 = (lane < 8) ? ws2[lane] : 0.f;
#pragma unroll
        for (int o = 4; o > 0; o >>= 1) {
            s  += __shfl_xor_sync(0xffffffffu, s, o);
            s2 += __shfl_xor_sync(0xffffffffu, s2, o);
        }
        if (lane == 0) { ws[0] = s; ws2[0] = s2; }
    }
    __syncthreads();
    float mu   = ws[0] * (1.0f / CDIM);
    float var  = ws2[0] * (1.0f / CDIM) - mu * mu;
    float rstd = rsqrtf(var + 1e-5f);
#pragma unroll
    for (int i = 0; i < 3; i++) {
        int c = threadIdx.x + i * 256;
        out[(size_t)row * CDIM + c] = to_tf32((v[i] - mu) * rstd * gam[c] + bet[c]);
    }
}

// ---------------- Flash attention: QK tf32, PV bf16 ----------------
#define LDK 68
#define OFF_Q 0
#define OFF_K (128 * LDK)
// bf16 regions (byte offsets). float region = (128+64)*68*4 = 52224 B.
#define VOFF_B 52224
#define LDPB 144                      // bf16 row stride in bytes (72 bf16)
#define POFF_B (VOFF_B + 64 * LDPB)   // 61440
#define ATT_SMEM (POFF_B + 128 * LDPB)  // 79872

__global__ __launch_bounds__(256, 2) void attn_mma(const float* __restrict__ Q,
                                                   const float* __restrict__ K,
                                                   const __nv_bfloat16* __restrict__ V,
                                                   float* __restrict__ O) {
    extern __shared__ float smf[];
    uint32_t sbase = smem_u32(smf);
    int tid = threadIdx.x, lane = tid & 31, wm = tid >> 5;
    int g = lane >> 2, t = lane & 3;
    int bh = blockIdx.y;
    int b = bh / HH, h = bh - b * HH;
    int qbase = blockIdx.x * 128;

    {
        const float* Qg = Q + ((size_t)bh * NSEQ + qbase) * DD;
#pragma unroll
        for (int i = 0; i < 8; i++) {
            int idx = tid + i * 256;
            int r = idx >> 4, c4 = idx & 15;
            *(float4*)&smf[OFF_Q + r * LDK + c4 * 4] =
                *(const float4*)(Qg + (size_t)r * DD + c4 * 4);
        }
    }

    float acc_o[8][4];
#pragma unroll
    for (int i = 0; i < 8; i++)
#pragma unroll
        for (int j = 0; j < 4; j++) acc_o[i][j] = 0.f;
    float m0r = -1e30f, m1r = -1e30f, l0 = 0.f, l1 = 0.f;

    const uint32_t qA = sbase + 4 * (OFF_Q + (wm * 16 + (lane & 15)) * LDK + ((lane >> 4) << 2));
    const uint32_t kA = sbase + 4 * (OFF_K + ((lane & 7) + ((lane >> 4) << 3)) * LDK + (((lane >> 3) & 1) << 2));
    // bf16 ldmatrix bases
    const uint32_t pA = sbase + POFF_B + (uint32_t)((wm * 16 + (lane & 15)) * LDPB + ((lane >> 4) << 4));
    const uint32_t vA = sbase + VOFF_B + (uint32_t)(((lane & 15)) * LDPB + ((lane >> 4) << 4));

    const float* Kbase = K + (size_t)bh * NSEQ * DD;
    const __nv_bfloat16* Vbase = V + (size_t)bh * DD * NSEQ;   // bf16 d-major

    for (int kt = 0; kt < NSEQ / 64; kt++) {
        // stage K tile [64 keys][64 d] fp32
#pragma unroll
        for (int i = 0; i < 4; i++) {
            int idx = tid + i * 256;
            int r = idx >> 4, c4 = idx & 15;
            *(float4*)&smf[OFF_K + r * LDK + c4 * 4] =
                *(const float4*)(Kbase + ((size_t)(kt * 64 + r)) * DD + c4 * 4);
        }
        // stage V tile [64 d][64 keys] bf16 — straight 16B copies
#pragma unroll
        for (int i = 0; i < 2; i++) {
            int idx = tid + i * 256;          // 512 uint4s: 64 rows x 8
            int r = idx >> 3, c = idx & 7;
            const uint4* src = (const uint4*)((const char*)Vbase + (size_t)r * (NSEQ * 2) + kt * 128 + c * 16);
            *(uint4*)((char*)smf + VOFF_B + r * LDPB + c * 16) = *src;
        }
        __syncthreads();

        // S = Q K^T (tf32)
        float s[8][4];
#pragma unroll
        for (int i = 0; i < 8; i++)
#pragma unroll
            for (int j = 0; j < 4; j++) s[i][j] = 0.f;
#pragma unroll
        for (int ks = 0; ks < 8; ks++) {
            uint32_t qa[4], kb[4][4];
            ldsm4(qa, qA + ks * 32);
#pragma unroll
            for (int p = 0; p < 4; p++)
                ldsm4(kb[p], kA + 4 * (p * 16 * LDK + ks * 8));
#pragma unroll
            for (int nt = 0; nt < 8; nt++)
                mma_tf32(s[nt], qa, &kb[nt >> 1][(nt & 1) * 2]);
        }

        // online softmax; write P to smem as bf16
        float mx0 = -1e30f, mx1 = -1e30f;
#pragma unroll
        for (int nt = 0; nt < 8; nt++) {
            mx0 = fmaxf(mx0, fmaxf(s[nt][0], s[nt][1]));
            mx1 = fmaxf(mx1, fmaxf(s[nt][2], s[nt][3]));
        }
        mx0 = fmaxf(mx0, __shfl_xor_sync(0xffffffffu, mx0, 1));
        mx0 = fmaxf(mx0, __shfl_xor_sync(0xffffffffu, mx0, 2));
        mx1 = fmaxf(mx1, __shfl_xor_sync(0xffffffffu, mx1, 1));
        mx1 = fmaxf(mx1, __shfl_xor_sync(0xffffffffu, mx1, 2));
        float nm0 = fmaxf(m0r, mx0), nm1 = fmaxf(m1r, mx1);
        float al0 = __expf(m0r - nm0), al1 = __expf(m1r - nm1);
        float ts0 = 0.f, ts1 = 0.f;
        char* Pw = (char*)smf + POFF_B + (wm * 16) * LDPB;
#pragma unroll
        for (int nt = 0; nt < 8; nt++) {
            float p00 = __expf(s[nt][0] - nm0);
            float p01 = __expf(s[nt][1] - nm0);
            float p10 = __expf(s[nt][2] - nm1);
            float p11 = __expf(s[nt][3] - nm1);
            ts0 += p00 + p01; ts1 += p10 + p11;
            int cb = (nt * 8 + 2 * t) * 2;
            *(uint32_t*)(Pw + g * LDPB + cb) = pack_bf16(p00, p01);
            *(uint32_t*)(Pw + (g + 8) * LDPB + cb) = pack_bf16(p10, p11);
        }
        ts0 += __shfl_xor_sync(0xffffffffu, ts0, 1);
        ts0 += __shfl_xor_sync(0xffffffffu, ts0, 2);
        ts1 += __shfl_xor_sync(0xffffffffu, ts1, 1);
        ts1 += __shfl_xor_sync(0xffffffffu, ts1, 2);
        l0 = l0 * al0 + ts0;
        l1 = l1 * al1 + ts1;
        m0r = nm0; m1r = nm1;
#pragma unroll
        for (int nt = 0; nt < 8; nt++) {
            acc_o[nt][0] *= al0; acc_o[nt][1] *= al0;
            acc_o[nt][2] *= al1; acc_o[nt][3] *= al1;
        }
        __syncwarp();

        // O += P V  (bf16 m16n8k16)
#pragma unroll
        for (int kk = 0; kk < 4; kk++) {
            uint32_t pa[4];
            ldsm4(pa, pA + kk * 32);
#pragma unroll
            for (int p = 0; p < 4; p++) {
                uint32_t vb[4];
                ldsm4(vb, vA + p * (16 * LDPB) + kk * 32);
                mma_bf16(acc_o[p * 2 + 0], pa, vb[0], vb[2]);
                mma_bf16(acc_o[p * 2 + 1], pa, vb[1], vb[3]);
            }
        }
        __syncthreads();
    }

    float inv0 = 1.0f / l0, inv1 = 1.0f / l1;
    int row0 = qbase + wm * 16 + g;
    float* Ob = O + ((size_t)b * NSEQ) * CDIM + h * DD;
#pragma unroll
    for (int nt = 0; nt < 8; nt++) {
        int col = nt * 8 + 2 * t;
        *(float2*)(Ob + (size_t)row0 * CDIM + col) =
            make_float2(to_tf32(acc_o[nt][0] * inv0), to_tf32(acc_o[nt][1] * inv0));
        *(float2*)(Ob + (size_t)(row0 + 8) * CDIM + col) =
            make_float2(to_tf32(acc_o[nt][2] * inv1), to_tf32(acc_o[nt][3] * inv1));
    }
}

// ---------------- host ----------------
extern "C" void kernel_launch(void* const* d_in, const int* in_sizes, int n_in,
                              void* d_out, int out_size) {
    const float* x      = (const float*)d_in[0];
    const float* ln1_g  = (const float*)d_in[1];
    const float* ln1_b  = (const float*)d_in[2];
    const float* qkv_w  = (const float*)d_in[3];
    const float* proj_w = (const float*)d_in[4];
    const float* proj_b = (const float*)d_in[5];
    const float* ln2_g  = (const float*)d_in[6];
    const float* ln2_b  = (const float*)d_in[7];
    const float* fc1_w  = (const float*)d_in[8];
    const float* fc1_b  = (const float*)d_in[9];
    const float* fc2_w  = (const float*)d_in[10];
    const float* fc2_b  = (const float*)d_in[11];
    float* out = (float*)d_out;

    float *h, *q, *k, *o, *x1, *hid, *wqkv, *wproj, *wfc1, *wfc2;
    __nv_bfloat16* vb;
    cudaGetSymbolAddress((void**)&h,    g_h);
    cudaGetSymbolAddress((void**)&q,    g_q);
    cudaGetSymbolAddress((void**)&k,    g_k);
    cudaGetSymbolAddress((void**)&vb,   g_vb);
    cudaGetSymbolAddress((void**)&o,    g_o);
    cudaGetSymbolAddress((void**)&x1,   g_x1);
    cudaGetSymbolAddress((void**)&hid,  g_hid);
    cudaGetSymbolAddress((void**)&wqkv, g_wqkv);
    cudaGetSymbolAddress((void**)&wproj, g_wproj);
    cudaGetSymbolAddress((void**)&wfc1, g_wfc1);
    cudaGetSymbolAddress((void**)&wfc2, g_wfc2);

    cudaFuncSetAttribute(attn_mma, cudaFuncAttributeMaxDynamicSharedMemorySize, ATT_SMEM);
    cudaFuncSetAttribute(gemm_cp<0>, cudaFuncAttributeMaxDynamicSharedMemorySize, GEMM_SMEM);
    cudaFuncSetAttribute(gemm_cp<1>, cudaFuncAttributeMaxDynamicSharedMemorySize, GEMM_SMEM);
    cudaFuncSetAttribute(gemm_cp<2>, cudaFuncAttributeMaxDynamicSharedMemorySize, GEMM_SMEM);

    int nmax = HIDD * CDIM;
    wcvt_kernel<<<dim3((nmax / 4 + 255) / 256, 4), 256>>>(
        qkv_w, wqkv, 3 * CDIM * CDIM, proj_w, wproj, CDIM * CDIM,
        fc1_w, wfc1, HIDD * CDIM, fc2_w, wfc2, CDIM * HIDD);
    ln_kernel<<<MROWS, 256>>>(x, ln1_g, ln1_b, h);
    gemm_cp<0><<<dim3(3 * CDIM / 128, MROWS / 128), 256, GEMM_SMEM>>>(
        h, wqkv, nullptr, nullptr, nullptr, MROWS, 3 * CDIM, CDIM, q, k, vb);
    attn_mma<<<dim3(NSEQ / 128, BB * HH), 256, ATT_SMEM>>>(q, k, vb, o);
    gemm_cp<1><<<dim3(CDIM / 128, MROWS / 128), 256, GEMM_SMEM>>>(
        o, wproj, proj_b, x, x1, MROWS, CDIM, CDIM, nullptr, nullptr, nullptr);
    ln_kernel<<<MROWS, 256>>>(x1, ln2_g, ln2_b, h);
    gemm_cp<2><<<dim3(HIDD / 128, MROWS / 128), 256, GEMM_SMEM>>>(
        h, wfc1, fc1_b, nullptr, hid, MROWS, HIDD, CDIM, nullptr, nullptr, nullptr);
    gemm_cp<1><<<dim3(CDIM / 128, MROWS / 128), 256, GEMM_SMEM>>>(
        hid, wfc2, fc2_b, x1, out, MROWS, CDIM, HIDD, nullptr, nullptr, nullptr);
}

// round 9
// speedup vs baseline: 1.3491x; 1.3491x over previous
#include <cuda_runtime.h>
#include <cstdint>
#include <math.h>

#define BB 4
#define NSEQ 2048
#define CDIM 768
#define HH 12
#define DD 64
#define HIDD 3072
#define MROWS (BB * NSEQ)   // 8192

// ---------------- scratch ----------------
__device__ float g_h[MROWS * CDIM];
__device__ float g_q[MROWS * CDIM];
__device__ float g_k[MROWS * CDIM];
__device__ float g_v[MROWS * CDIM];     // [B,H,D,N] d-major
__device__ float g_o[MROWS * CDIM];
__device__ float g_x1[MROWS * CDIM];
__device__ float g_hid[MROWS * HIDD];
// tf32-rounded weights
__device__ float g_wqkv[3 * CDIM * CDIM];
__device__ float g_wproj[CDIM * CDIM];
__device__ float g_wfc1[HIDD * CDIM];
__device__ float g_wfc2[CDIM * HIDD];

__device__ __forceinline__ float to_tf32(float x) {
    float y;
    asm("cvt.rna.tf32.f32 %0, %1;" : "=f"(y) : "f"(x));
    return y;
}
__device__ __forceinline__ uint32_t smem_u32(const void* p) {
    uint32_t a;
    asm("{ .reg .u64 t; cvta.to.shared.u64 t, %1; cvt.u32.u64 %0, t; }" : "=r"(a) : "l"(p));
    return a;
}
__device__ __forceinline__ void mma_tf32(float* d, const uint32_t* a, const uint32_t* b) {
    asm volatile(
        "mma.sync.aligned.m16n8k8.row.col.f32.tf32.tf32.f32 "
        "{%0,%1,%2,%3}, {%4,%5,%6,%7}, {%8,%9}, {%0,%1,%2,%3};"
        : "+f"(d[0]), "+f"(d[1]), "+f"(d[2]), "+f"(d[3])
        : "r"(a[0]), "r"(a[1]), "r"(a[2]), "r"(a[3]), "r"(b[0]), "r"(b[1]));
}
__device__ __forceinline__ void ldsm4(uint32_t* r, uint32_t addr) {
    asm volatile("ldmatrix.sync.aligned.m8n8.x4.shared.b16 {%0,%1,%2,%3}, [%4];"
                 : "=r"(r[0]), "=r"(r[1]), "=r"(r[2]), "=r"(r[3]) : "r"(addr));
}
__device__ __forceinline__ void cp16(uint32_t dst, const float* src) {
    asm volatile("cp.async.cg.shared.global [%0], [%1], 16;"
                 :: "r"(dst), "l"(__cvta_generic_to_global(src)));
}
#define CP_COMMIT() asm volatile("cp.async.commit_group;" ::: "memory")
#define CP_WAIT1()  asm volatile("cp.async.wait_group 1;" ::: "memory")
#define CP_WAIT0()  asm volatile("cp.async.wait_group 0;" ::: "memory")

// ---------------- weight tf32 pre-round ----------------
__global__ __launch_bounds__(256) void wcvt_kernel(
    const float* s0, float* d0, int n0, const float* s1, float* d1, int n1,
    const float* s2, float* d2, int n2, const float* s3, float* d3, int n3) {
    const float* s; float* d; int n;
    switch (blockIdx.y) {
        case 0: s = s0; d = d0; n = n0; break;
        case 1: s = s1; d = d1; n = n1; break;
        case 2: s = s2; d = d2; n = n2; break;
        default: s = s3; d = d3; n = n3; break;
    }
    int i = (blockIdx.x * 256 + threadIdx.x) * 4;
    if (i < n) {
        float4 v = *(const float4*)(s + i);
        v.x = to_tf32(v.x); v.y = to_tf32(v.y); v.z = to_tf32(v.z); v.w = to_tf32(v.w);
        *(float4*)(d + i) = v;
    }
}

// ---------------- cp.async tensor-core GEMM: C = A[M,K] * W[Nn,K]^T ----------------
#define GS 3
#define STG_B 32768
#define GEMM_SMEM (GS * STG_B)

template <int EPI>
__global__ __launch_bounds__(256, 2) void gemm_cp(
    const float* __restrict__ A, const float* __restrict__ W,
    const float* __restrict__ bias, const float* __restrict__ res,
    float* __restrict__ C, int M, int Nn, int K,
    float* __restrict__ qout, float* __restrict__ kout, float* __restrict__ vout) {
    extern __shared__ char sm[];
    uint32_t sb = smem_u32(sm);
    int tid = threadIdx.x, lane = tid & 31, wid = tid >> 5;
    int warpM = wid & 1, warpN = wid >> 1;
    int g = lane >> 2, t = lane & 3;
    int rowBase = blockIdx.y * 128, colBase = blockIdx.x * 128;

    float acc[4][4][4];
#pragma unroll
    for (int i = 0; i < 4; i++)
#pragma unroll
        for (int j = 0; j < 4; j++)
#pragma unroll
            for (int e = 0; e < 4; e++) acc[i][j][e] = 0.f;

    const int r0 = tid >> 3;
    const int c16 = tid & 7;
    const uint32_t csw = (uint32_t)((c16 ^ (r0 & 7)) << 4);
    const float* Ab = A + (size_t)rowBase * K + c16 * 4;
    const float* Wb = W + (size_t)colBase * K + c16 * 4;

    const int r7 = lane & 7;
    const int hiA = lane >> 4;
    const int hiB = (lane >> 3) & 1;
    uint32_t rbA[4], rbB[2];
#pragma unroll
    for (int mt = 0; mt < 4; mt++)
        rbA[mt] = (uint32_t)((warpM * 64 + mt * 16 + (lane & 15)) * 128);
#pragma unroll
    for (int p = 0; p < 2; p++)
        rbB[p] = (uint32_t)((warpN * 32 + p * 16 + (lane & 7) + ((lane >> 4) << 3)) * 128) + 16384;

    const int nc = K >> 5;
#pragma unroll
    for (int s = 0; s < GS - 1; s++) {
        uint32_t sA = sb + s * STG_B;
        const float* Ac = Ab + s * 32;
        const float* Wc = Wb + s * 32;
#pragma unroll
        for (int i = 0; i < 4; i++) {
            int r = r0 + i * 32;
            cp16(sA + r * 128 + csw, Ac + (size_t)r * K);
            cp16(sA + 16384 + r * 128 + csw, Wc + (size_t)r * K);
        }
        CP_COMMIT();
    }

    for (int c = 0; c < nc; c++) {
        CP_WAIT1();
        __syncthreads();
        int nxt = c + GS - 1;
        if (nxt < nc) {
            uint32_t sA = sb + (nxt % GS) * STG_B;
            const float* Ac = Ab + nxt * 32;
            const float* Wc = Wb + nxt * 32;
#pragma unroll
            for (int i = 0; i < 4; i++) {
                int r = r0 + i * 32;
                cp16(sA + r * 128 + csw, Ac + (size_t)r * K);
                cp16(sA + 16384 + r * 128 + csw, Wc + (size_t)r * K);
            }
        }
        CP_COMMIT();
        uint32_t stg = sb + (c % GS) * STG_B;
#pragma unroll
        for (int ks = 0; ks < 4; ks++) {
            uint32_t colA = (uint32_t)((((2 * ks + hiA) ^ r7)) << 4);
            uint32_t colB = (uint32_t)((((2 * ks + hiB) ^ r7)) << 4);
            uint32_t af[4][4], bf[2][4];
#pragma unroll
            for (int mt = 0; mt < 4; mt++) ldsm4(af[mt], stg + rbA[mt] + colA);
#pragma unroll
            for (int p = 0; p < 2; p++) ldsm4(bf[p], stg + rbB[p] + colB);
#pragma unroll
            for (int mt = 0; mt < 4; mt++)
#pragma unroll
                for (int nt = 0; nt < 4; nt++)
                    mma_tf32(acc[mt][nt], af[mt], &bf[nt >> 1][(nt & 1) * 2]);
        }
    }

#pragma unroll
    for (int mt = 0; mt < 4; mt++) {
        int rlo = rowBase + warpM * 64 + mt * 16 + g;
#pragma unroll
        for (int nt = 0; nt < 4; nt++) {
            int colb = colBase + warpN * 32 + nt * 8 + t * 2;
#pragma unroll
            for (int half = 0; half < 2; half++) {
                int row = rlo + half * 8;
                float v0 = acc[mt][nt][half * 2 + 0];
                float v1 = acc[mt][nt][half * 2 + 1];
                if (EPI == 0) {
                    int which = colb / CDIM;
                    int rem = colb - which * CDIM;
                    int h = rem >> 6, d0 = rem & 63;
                    int bq = row >> 11, n = row & 2047;
                    if (which == 2) {
                        float* dst = vout + (((size_t)bq * HH + h) * DD + d0) * NSEQ + n;
                        dst[0] = to_tf32(v0);
                        dst[NSEQ] = to_tf32(v1);
                    } else {
                        float scale = (which == 0) ? 0.125f : 1.0f;
                        float* dst = (which == 0 ? qout : kout) +
                                     ((((size_t)bq * HH + h) * NSEQ + n) * DD + d0);
                        *(float2*)dst = make_float2(to_tf32(v0 * scale), to_tf32(v1 * scale));
                    }
                } else if (EPI == 1) {
                    float2 bv = *(const float2*)(bias + colb);
                    float2 rv = *(const float2*)(res + (size_t)row * Nn + colb);
                    *(float2*)(C + (size_t)row * Nn + colb) =
                        make_float2(v0 + bv.x + rv.x, v1 + bv.y + rv.y);
                } else {
                    float2 bv = *(const float2*)(bias + colb);
                    float u0 = v0 + bv.x, u1 = v1 + bv.y;
                    float2 o;
                    o.x = to_tf32(0.5f * u0 * (1.0f + erff(u0 * 0.70710678f)));
                    o.y = to_tf32(0.5f * u1 * (1.0f + erff(u1 * 0.70710678f)));
                    *(float2*)(C + (size_t)row * Nn + colb) = o;
                }
            }
        }
    }
}

// ---------------- LayerNorm (tf32-rounded output) ----------------
__global__ __launch_bounds__(256) void ln_kernel(const float* __restrict__ X,
                                                 const float* __restrict__ gam,
                                                 const float* __restrict__ bet,
                                                 float* __restrict__ out) {
    int row = blockIdx.x;
    const float* xr = X + (size_t)row * CDIM;
    float v[3];
    float s = 0.f, s2 = 0.f;
#pragma unroll
    for (int i = 0; i < 3; i++) {
        v[i] = xr[threadIdx.x + i * 256];
        s += v[i];
        s2 += v[i] * v[i];
    }
#pragma unroll
    for (int o = 16; o > 0; o >>= 1) {
        s  += __shfl_xor_sync(0xffffffffu, s, o);
        s2 += __shfl_xor_sync(0xffffffffu, s2, o);
    }
    __shared__ float ws[8], ws2[8];
    int wid = threadIdx.x >> 5, lane = threadIdx.x & 31;
    if (lane == 0) { ws[wid] = s; ws2[wid] = s2; }
    __syncthreads();
    if (wid == 0) {
        s  = (lane < 8) ? ws[lane] : 0.f;
        s2 = (lane < 8) ? ws2[lane] : 0.f;
#pragma unroll
        for (int o = 4; o > 0; o >>= 1) {
            s  += __shfl_xor_sync(0xffffffffu, s, o);
            s2 += __shfl_xor_sync(0xffffffffu, s2, o);
        }
        if (lane == 0) { ws[0] = s; ws2[0] = s2; }
    }
    __syncthreads();
    float mu   = ws[0] * (1.0f / CDIM);
    float var  = ws2[0] * (1.0f / CDIM) - mu * mu;
    float rstd = rsqrtf(var + 1e-5f);
#pragma unroll
    for (int i = 0; i < 3; i++) {
        int c = threadIdx.x + i * 256;
        out[(size_t)row * CDIM + c] = to_tf32((v[i] - mu) * rstd * gam[c] + bet[c]);
    }
}

// ---------------- Flash attention: Q frags in regs, cp.async double-buffered K/V ----------------
#define LDK 68
#define OFF_K 0                     // 2 buffers x 4352 floats
#define OFF_V 8704                  // 2 buffers x 4352 floats
#define OFF_P 17408                 // 128 x 68 floats
#define KV_STRIDE_B 17408           // 4352 floats * 4 bytes
#define ATT_SMEM ((OFF_P + 128 * LDK) * 4)   // 104448

__global__ __launch_bounds__(256, 2) void attn_mma(const float* __restrict__ Q,
                                                   const float* __restrict__ K,
                                                   const float* __restrict__ V,
                                                   float* __restrict__ O) {
    extern __shared__ float smf[];
    uint32_t sbase = smem_u32(smf);
    int tid = threadIdx.x, lane = tid & 31, wm = tid >> 5;
    int g = lane >> 2, t = lane & 3;
    int bh = blockIdx.y;
    int b = bh / HH, h = bh - b * HH;
    int qbase = blockIdx.x * 128;

    const float* Kbase = K + (size_t)bh * NSEQ * DD;
    const float* Vbase = V + (size_t)bh * DD * NSEQ;   // d-major

    // staging map: 1024 16B-chunks each for K and V; 4 per thread
    const int sr = tid >> 2;           // 0..63 row
    const int sc = tid & 3;            // 0..3 -> chunk pairs (c = sc*4 + i)
    // Q fragments: hoisted into registers for the whole kernel
    uint32_t qf[8][4];
    {
        const float* Qg = Q + ((size_t)bh * NSEQ + qbase + wm * 16) * DD;
#pragma unroll
        for (int ks = 0; ks < 8; ks++) {
            qf[ks][0] = __float_as_uint(Qg[(size_t)g * DD + ks * 8 + t]);
            qf[ks][1] = __float_as_uint(Qg[(size_t)(g + 8) * DD + ks * 8 + t]);
            qf[ks][2] = __float_as_uint(Qg[(size_t)g * DD + ks * 8 + t + 4]);
            qf[ks][3] = __float_as_uint(Qg[(size_t)(g + 8) * DD + ks * 8 + t + 4]);
        }
    }

    float acc_o[8][4];
#pragma unroll
    for (int i = 0; i < 8; i++)
#pragma unroll
        for (int j = 0; j < 4; j++) acc_o[i][j] = 0.f;
    float m0r = -1e30f, m1r = -1e30f, l0 = 0.f, l1 = 0.f;

    const uint32_t kA0 = sbase + 4 * (OFF_K + ((lane & 7) + ((lane >> 4) << 3)) * LDK + (((lane >> 3) & 1) << 2));
    const uint32_t vA0 = sbase + 4 * (OFF_V + ((lane & 7) + ((lane >> 4) << 3)) * LDK + (((lane >> 3) & 1) << 2));
    const uint32_t pA = sbase + 4 * (OFF_P + (wm * 16 + (lane & 15)) * LDK + ((lane >> 4) << 2));

    // prologue: stage tile 0 into buffer 0
    {
        const float* Ks = Kbase + (size_t)sr * DD + sc * 16;
        const float* Vs = Vbase + (size_t)sr * NSEQ + sc * 16;
        uint32_t kd = sbase + 4 * (OFF_K + sr * LDK) + sc * 64;
        uint32_t vd = sbase + 4 * (OFF_V + sr * LDK) + sc * 64;
#pragma unroll
        for (int i = 0; i < 4; i++) {
            cp16(kd + i * 16, Ks + i * 4);
            cp16(vd + i * 16, Vs + i * 4);
        }
        CP_COMMIT();
    }

    for (int kt = 0; kt < NSEQ / 64; kt++) {
        int buf = kt & 1;
        CP_WAIT0();
        __syncthreads();
        if (kt + 1 < NSEQ / 64) {
            int nb = buf ^ 1;
            const float* Ks = Kbase + (size_t)(kt * 64 + 64 + sr) * DD + sc * 16;
            const float* Vs = Vbase + (size_t)sr * NSEQ + (kt * 64 + 64) + sc * 16;
            uint32_t kd = sbase + nb * KV_STRIDE_B + 4 * (OFF_K + sr * LDK) + sc * 64;
            uint32_t vd = sbase + nb * KV_STRIDE_B + 4 * (OFF_V + sr * LDK) + sc * 64;
#pragma unroll
            for (int i = 0; i < 4; i++) {
                cp16(kd + i * 16, Ks + i * 4);
                cp16(vd + i * 16, Vs + i * 4);
            }
        }
        CP_COMMIT();

        uint32_t kAb = kA0 + buf * KV_STRIDE_B;
        uint32_t vAb = vA0 + buf * KV_STRIDE_B;

        // S = Q K^T (tf32), Q frags from registers
        float s[8][4];
#pragma unroll
        for (int i = 0; i < 8; i++)
#pragma unroll
            for (int j = 0; j < 4; j++) s[i][j] = 0.f;
#pragma unroll
        for (int ks = 0; ks < 8; ks++) {
            uint32_t kb[4][4];
#pragma unroll
            for (int p = 0; p < 4; p++)
                ldsm4(kb[p], kAb + 4 * (p * 16 * LDK + ks * 8));
#pragma unroll
            for (int nt = 0; nt < 8; nt++)
                mma_tf32(s[nt], qf[ks], &kb[nt >> 1][(nt & 1) * 2]);
        }

        // online softmax
        float mx0 = -1e30f, mx1 = -1e30f;
#pragma unroll
        for (int nt = 0; nt < 8; nt++) {
            mx0 = fmaxf(mx0, fmaxf(s[nt][0], s[nt][1]));
            mx1 = fmaxf(mx1, fmaxf(s[nt][2], s[nt][3]));
        }
        mx0 = fmaxf(mx0, __shfl_xor_sync(0xffffffffu, mx0, 1));
        mx0 = fmaxf(mx0, __shfl_xor_sync(0xffffffffu, mx0, 2));
        mx1 = fmaxf(mx1, __shfl_xor_sync(0xffffffffu, mx1, 1));
        mx1 = fmaxf(mx1, __shfl_xor_sync(0xffffffffu, mx1, 2));
        float nm0 = fmaxf(m0r, mx0), nm1 = fmaxf(m1r, mx1);
        float al0 = __expf(m0r - nm0), al1 = __expf(m1r - nm1);
        float ts0 = 0.f, ts1 = 0.f;
        float* Pw = &smf[OFF_P + (wm * 16) * LDK];
#pragma unroll
        for (int nt = 0; nt < 8; nt++) {
            float p00 = __expf(s[nt][0] - nm0);
            float p01 = __expf(s[nt][1] - nm0);
            float p10 = __expf(s[nt][2] - nm1);
            float p11 = __expf(s[nt][3] - nm1);
            ts0 += p00 + p01; ts1 += p10 + p11;
            *(float2*)&Pw[g * LDK + nt * 8 + 2 * t] = make_float2(to_tf32(p00), to_tf32(p01));
            *(float2*)&Pw[(g + 8) * LDK + nt * 8 + 2 * t] = make_float2(to_tf32(p10), to_tf32(p11));
        }
        ts0 += __shfl_xor_sync(0xffffffffu, ts0, 1);
        ts0 += __shfl_xor_sync(0xffffffffu, ts0, 2);
        ts1 += __shfl_xor_sync(0xffffffffu, ts1, 1);
        ts1 += __shfl_xor_sync(0xffffffffu, ts1, 2);
        l0 = l0 * al0 + ts0;
        l1 = l1 * al1 + ts1;
        m0r = nm0; m1r = nm1;
#pragma unroll
        for (int nt = 0; nt < 8; nt++) {
            acc_o[nt][0] *= al0; acc_o[nt][1] *= al0;
            acc_o[nt][2] *= al1; acc_o[nt][3] *= al1;
        }
        __syncwarp();

        // O += P V
#pragma unroll
        for (int kk = 0; kk < 8; kk++) {
            uint32_t pa[4], vb[4][4];
            ldsm4(pa, pA + kk * 32);
#pragma unroll
            for (int p = 0; p < 4; p++)
                ldsm4(vb[p], vAb + 4 * (p * 16 * LDK + kk * 8));
#pragma unroll
            for (int nt = 0; nt < 8; nt++)
                mma_tf32(acc_o[nt], pa, &vb[nt >> 1][(nt & 1) * 2]);
        }
    }

    float inv0 = 1.0f / l0, inv1 = 1.0f / l1;
    int row0 = qbase + wm * 16 + g;
    float* Ob = O + ((size_t)b * NSEQ) * CDIM + h * DD;
#pragma unroll
    for (int nt = 0; nt < 8; nt++) {
        int col = nt * 8 + 2 * t;
        *(float2*)(Ob + (size_t)row0 * CDIM + col) =
            make_float2(to_tf32(acc_o[nt][0] * inv0), to_tf32(acc_o[nt][1] * inv0));
        *(float2*)(Ob + (size_t)(row0 + 8) * CDIM + col) =
            make_float2(to_tf32(acc_o[nt][2] * inv1), to_tf32(acc_o[nt][3] * inv1));
    }
}

// ---------------- host ----------------
extern "C" void kernel_launch(void* const* d_in, const int* in_sizes, int n_in,
                              void* d_out, int out_size) {
    const float* x      = (const float*)d_in[0];
    const float* ln1_g  = (const float*)d_in[1];
    const float* ln1_b  = (const float*)d_in[2];
    const float* qkv_w  = (const float*)d_in[3];
    const float* proj_w = (const float*)d_in[4];
    const float* proj_b = (const float*)d_in[5];
    const float* ln2_g  = (const float*)d_in[6];
    const float* ln2_b  = (const float*)d_in[7];
    const float* fc1_w  = (const float*)d_in[8];
    const float* fc1_b  = (const float*)d_in[9];
    const float* fc2_w  = (const float*)d_in[10];
    const float* fc2_b  = (const float*)d_in[11];
    float* out = (float*)d_out;

    float *h, *q, *k, *v, *o, *x1, *hid, *wqkv, *wproj, *wfc1, *wfc2;
    cudaGetSymbolAddress((void**)&h,    g_h);
    cudaGetSymbolAddress((void**)&q,    g_q);
    cudaGetSymbolAddress((void**)&k,    g_k);
    cudaGetSymbolAddress((void**)&v,    g_v);
    cudaGetSymbolAddress((void**)&o,    g_o);
    cudaGetSymbolAddress((void**)&x1,   g_x1);
    cudaGetSymbolAddress((void**)&hid,  g_hid);
    cudaGetSymbolAddress((void**)&wqkv, g_wqkv);
    cudaGetSymbolAddress((void**)&wproj, g_wproj);
    cudaGetSymbolAddress((void**)&wfc1, g_wfc1);
    cudaGetSymbolAddress((void**)&wfc2, g_wfc2);

    cudaFuncSetAttribute(attn_mma, cudaFuncAttributeMaxDynamicSharedMemorySize, ATT_SMEM);
    cudaFuncSetAttribute(gemm_cp<0>, cudaFuncAttributeMaxDynamicSharedMemorySize, GEMM_SMEM);
    cudaFuncSetAttribute(gemm_cp<1>, cudaFuncAttributeMaxDynamicSharedMemorySize, GEMM_SMEM);
    cudaFuncSetAttribute(gemm_cp<2>, cudaFuncAttributeMaxDynamicSharedMemorySize, GEMM_SMEM);

    int nmax = HIDD * CDIM;
    wcvt_kernel<<<dim3((nmax / 4 + 255) / 256, 4), 256>>>(
        qkv_w, wqkv, 3 * CDIM * CDIM, proj_w, wproj, CDIM * CDIM,
        fc1_w, wfc1, HIDD * CDIM, fc2_w, wfc2, CDIM * HIDD);
    ln_kernel<<<MROWS, 256>>>(x, ln1_g, ln1_b, h);
    gemm_cp<0><<<dim3(3 * CDIM / 128, MROWS / 128), 256, GEMM_SMEM>>>(
        h, wqkv, nullptr, nullptr, nullptr, MROWS, 3 * CDIM, CDIM, q, k, v);
    attn_mma<<<dim3(NSEQ / 128, BB * HH), 256, ATT_SMEM>>>(q, k, v, o);
    gemm_cp<1><<<dim3(CDIM / 128, MROWS / 128), 256, GEMM_SMEM>>>(
        o, wproj, proj_b, x, x1, MROWS, CDIM, CDIM, nullptr, nullptr, nullptr);
    ln_kernel<<<MROWS, 256>>>(x1, ln2_g, ln2_b, h);
    gemm_cp<2><<<dim3(HIDD / 128, MROWS / 128), 256, GEMM_SMEM>>>(
        h, wfc1, fc1_b, nullptr, hid, MROWS, HIDD, CDIM, nullptr, nullptr, nullptr);
    gemm_cp<1><<<dim3(CDIM / 128, MROWS / 128), 256, GEMM_SMEM>>>(
        hid, wfc2, fc2_b, x1, out, MROWS, CDIM, HIDD, nullptr, nullptr, nullptr);
}